// round 7
// baseline (speedup 1.0000x reference)
#include <cuda_runtime.h>
#include <cuda_bf16.h>
#include <cstdint>

// Problem constants (fixed by the reference)
#define N_NODES   100000
#define FDIM      512
#define EDIM      256
#define NB        16384
#define S_SAMP    10

// ---------------- device scratch (no allocations allowed) ----------------
__device__ char  g_a1[(size_t)NB * FDIM];    // agg limb1 (int8)
__device__ char  g_a2[(size_t)NB * FDIM];    // agg limb2 (int8, /128)
__device__ char  g_w1[(size_t)EDIM * FDIM];  // weight limb1
__device__ char  g_w2[(size_t)EDIM * FDIM];  // weight limb2
__device__ float g_sa[NB];                   // per-batch-row scale
__device__ float g_sw[EDIM];                 // per-embed-row scale
__device__ int   g_tileCnt[NB / 64];         // 256 per-b-tile gather counters
__device__ int   g_wqCnt;                    // weight-quant row counter

static __device__ __forceinline__ uint32_t smem_u32(const void* p) {
    uint32_t a;
    asm("{ .reg .u64 t; cvta.to.shared.u64 t, %1; cvt.u32.u64 %0, t; }"
        : "=r"(a) : "l"(p));
    return a;
}
static __device__ __forceinline__ float warp_max(float v) {
#pragma unroll
    for (int o = 16; o > 0; o >>= 1)
        v = fmaxf(v, __shfl_xor_sync(0xffffffffu, v, o));
    return v;
}

// GEMM geometry
#define BM 128
#define BN 64
#define KCB 64
#define NCHUNK (FDIM / KCB)    // 8
#define STRIDE 80              // padded smem row stride (bytes)
#define OFF_W1 0
#define OFF_W2 (BM * STRIDE)
#define OFF_A1 (2 * BM * STRIDE)
#define OFF_A2 (2 * BM * STRIDE + BN * STRIDE)
#define STAGE  (2 * BM * STRIDE + 2 * BN * STRIDE)  // 30720
#define SMEMSZ (2 * STAGE)                           // 61440
#define NTILES ((NB / BN) * (EDIM / BM))             // 512

__global__ void k_zero() {
    int t = threadIdx.x;
    if (t < NB / 64) g_tileCnt[t] = 0;
    if (t == NB / 64) g_wqCnt = 0;
}

// ==========================================================================
// Persistent fused kernel: wq -> gather (flagged) -> gemm (flag-consuming).
// grid = 2 * SM count; __launch_bounds__(256,2) guarantees full residency,
// so every producer block is running while consumers spin => no deadlock.
// ==========================================================================
__global__ __launch_bounds__(256, 2) void k_fused(const float* __restrict__ feat,
                                                  const float* __restrict__ W,
                                                  const int* __restrict__ idxw,
                                                  float* __restrict__ out) {
    extern __shared__ char sm[];
    __shared__ float s_red[8];
    __shared__ int   s_ids[4][16];
    __shared__ int   s_misc;

    const int tid = threadIdx.x;
    const int bid = blockIdx.x;
    const int G = gridDim.x;
    const int lane = tid & 31;
    const int wrp = tid >> 5;

    // ---------------- Phase A: weight quantization (1 row / block pass) ----
    for (int e = bid; e < EDIM; e += G) {
        float2 w = *(const float2*)(W + (size_t)e * FDIM + tid * 2);
        float lm = fmaxf(fabsf(w.x), fabsf(w.y));
        lm = warp_max(lm);
        if (lane == 0) s_red[wrp] = lm;
        __syncthreads();
        float rmax = s_red[0];
#pragma unroll
        for (int i = 1; i < 8; i++) rmax = fmaxf(rmax, s_red[i]);
        rmax = fmaxf(rmax, 1e-30f);
        float qs = 127.0f / rmax;

        union { char c[2]; short s; } L1, L2;
        float qf, r; int i1, i2;
        qf = w.x * qs; i1 = __float2int_rn(qf); r = (qf - (float)i1) * 128.f;
        i2 = __float2int_rn(r); L1.c[0] = (char)i1; L2.c[0] = (char)i2;
        qf = w.y * qs; i1 = __float2int_rn(qf); r = (qf - (float)i1) * 128.f;
        i2 = __float2int_rn(r); L1.c[1] = (char)i1; L2.c[1] = (char)i2;
        size_t o = (size_t)e * FDIM + tid * 2;
        *(short*)(g_w1 + o) = L1.s;
        *(short*)(g_w2 + o) = L2.s;
        if (tid == 0) g_sw[e] = rmax * (1.0f / 127.0f);
        __syncthreads();
        if (tid == 0) { __threadfence(); atomicAdd(&g_wqCnt, 1); }
    }

    // ---------------- index dtype detect (once per block) ------------------
    if (tid == 0) {
        int ok = 1;
#pragma unroll
        for (int s = 0; s < S_SAMP; s++) {
            long long v = (long long)(unsigned)idxw[2 * s] |
                          ((long long)idxw[2 * s + 1] << 32);
            if (v < 0 || v >= N_NODES) ok = 0;
        }
        s_misc = ok;
    }
    __syncthreads();
    const int is64 = s_misc;

    // ---------------- Phase B: gather units (4 rows each), round-robin -----
    // Round-robin => low batch tiles complete earliest (progressive supply).
    const int ty = tid >> 6;        // row within unit (0..3)
    const int tx = tid & 63;        // 64 threads per row, 8 floats each
    for (int u = bid; u < NB / 4; u += G) {
        int b = u * 4 + ty;
        if (tx < S_SAMP) {
            int p = b * S_SAMP + tx;
            s_ids[ty][tx] = is64 ? idxw[2 * p] : idxw[p];
        }
        __syncthreads();

        float4 a0 = make_float4(0.f, 0.f, 0.f, 0.f);
        float4 a1 = make_float4(0.f, 0.f, 0.f, 0.f);
#pragma unroll
        for (int s = 0; s < S_SAMP; s++) {
            const float* p = feat + (size_t)s_ids[ty][s] * FDIM + tx * 8;
            float4 v0 = *(const float4*)p;
            float4 v1 = *(const float4*)(p + 4);
            a0.x += v0.x; a0.y += v0.y; a0.z += v0.z; a0.w += v0.w;
            a1.x += v1.x; a1.y += v1.y; a1.z += v1.z; a1.w += v1.w;
        }
        const float inv10 = 1.0f / (float)S_SAMP;
        float m[8] = { a0.x * inv10, a0.y * inv10, a0.z * inv10, a0.w * inv10,
                       a1.x * inv10, a1.y * inv10, a1.z * inv10, a1.w * inv10 };

        float lm = 0.f;
#pragma unroll
        for (int j = 0; j < 8; j++) lm = fmaxf(lm, fabsf(m[j]));
        lm = warp_max(lm);                        // row ty = warps 2ty, 2ty+1
        if (lane == 0) s_red[wrp] = lm;
        __syncthreads();
        float rmax = fmaxf(s_red[2 * ty], s_red[2 * ty + 1]);
        rmax = fmaxf(rmax, 1e-30f);
        float qs = 127.0f / rmax;

        union { char c[8]; uint2 u2; } L1, L2;
#pragma unroll
        for (int j = 0; j < 8; j++) {
            float qf = m[j] * qs;
            int i1 = __float2int_rn(qf);
            int i2 = __float2int_rn((qf - (float)i1) * 128.f);
            L1.c[j] = (char)i1; L2.c[j] = (char)i2;
        }
        size_t o = (size_t)b * FDIM + tx * 8;
        *(uint2*)(g_a1 + o) = L1.u2;
        *(uint2*)(g_a2 + o) = L2.u2;
        if (tx == 0) g_sa[b] = rmax * (1.0f / 127.0f);
        __syncthreads();
        if (tid == 0) { __threadfence(); atomicAdd(&g_tileCnt[u >> 4], 1); }
    }

    // ---------------- Phase C: GEMM tiles, flag-gated -----------------------
    const int wid = wrp;
    const int wm = wid & 3;            // 32-row slab (E)
    const int wn = wid >> 2;           // 32-col slab (B)
    uint32_t sb = smem_u32(sm);

    // copy slots
    int ar0 = (tid + 0) >> 2, ac0 = (tid + 0) & 3;
    int ar1 = (tid + 256) >> 2, ac1 = (tid + 256) & 3;
    int br = tid >> 2, bc = tid & 3;

    int aRow = lane & 15;
    int aCol = (lane >> 4) * 16;
    int bRow = (lane & 7) + ((lane >> 4) << 3);
    int bCol = ((lane >> 3) & 1) * 16;

    for (int T = bid; T < NTILES; T += G) {
        int nt = T >> 1;               // b-tile (progressive readiness order)
        int mt = T & 1;
        int m0 = mt * BM;
        int n0 = nt * BN;

        // wait for this tile's inputs
        if (tid == 0) {
            volatile int* tc = (volatile int*)&g_tileCnt[nt];
            volatile int* wc = (volatile int*)&g_wqCnt;
            while (*tc < 16 || *wc < EDIM) {}
            __threadfence();
        }
        __syncthreads();               // also guards smem reuse across tiles

        auto issue = [&](int c, int buf) {
            int kc = c * KCB;
            uint32_t d = sb + buf * STAGE;
            const char* w1p = g_w1 + (size_t)m0 * FDIM + kc;
            const char* w2p = g_w2 + (size_t)m0 * FDIM + kc;
            const char* a1p = g_a1 + (size_t)n0 * FDIM + kc;
            const char* a2p = g_a2 + (size_t)n0 * FDIM + kc;
            asm volatile("cp.async.cg.shared.global [%0], [%1], 16;"
                         :: "r"(d + OFF_W1 + (uint32_t)(ar0 * STRIDE + ac0 * 16)),
                            "l"(w1p + (size_t)ar0 * FDIM + ac0 * 16));
            asm volatile("cp.async.cg.shared.global [%0], [%1], 16;"
                         :: "r"(d + OFF_W1 + (uint32_t)(ar1 * STRIDE + ac1 * 16)),
                            "l"(w1p + (size_t)ar1 * FDIM + ac1 * 16));
            asm volatile("cp.async.cg.shared.global [%0], [%1], 16;"
                         :: "r"(d + OFF_W2 + (uint32_t)(ar0 * STRIDE + ac0 * 16)),
                            "l"(w2p + (size_t)ar0 * FDIM + ac0 * 16));
            asm volatile("cp.async.cg.shared.global [%0], [%1], 16;"
                         :: "r"(d + OFF_W2 + (uint32_t)(ar1 * STRIDE + ac1 * 16)),
                            "l"(w2p + (size_t)ar1 * FDIM + ac1 * 16));
            asm volatile("cp.async.cg.shared.global [%0], [%1], 16;"
                         :: "r"(d + OFF_A1 + (uint32_t)(br * STRIDE + bc * 16)),
                            "l"(a1p + (size_t)br * FDIM + bc * 16));
            asm volatile("cp.async.cg.shared.global [%0], [%1], 16;"
                         :: "r"(d + OFF_A2 + (uint32_t)(br * STRIDE + bc * 16)),
                            "l"(a2p + (size_t)br * FDIM + bc * 16));
            asm volatile("cp.async.commit_group;");
        };

        int accM[2][4][4], accX[2][4][4];
#pragma unroll
        for (int i = 0; i < 2; i++)
#pragma unroll
            for (int j = 0; j < 4; j++)
#pragma unroll
                for (int q = 0; q < 4; q++) { accM[i][j][q] = 0; accX[i][j][q] = 0; }

        issue(0, 0);
        issue(1, 1);

        for (int c = 0; c < NCHUNK; c++) {
            if (c == NCHUNK - 1) asm volatile("cp.async.wait_group 0;");
            else                 asm volatile("cp.async.wait_group 1;");
            __syncthreads();

            uint32_t base = sb + (c & 1) * STAGE;
#pragma unroll
            for (int ks = 0; ks < KCB; ks += 32) {
                uint32_t w1F[2][4], w2F[2][4], b1F[4][2], b2F[4][2];
#pragma unroll
                for (int mi = 0; mi < 2; mi++) {
                    uint32_t ra = (uint32_t)((wm * 32 + mi * 16 + aRow) * STRIDE +
                                             ks + aCol);
                    asm volatile("ldmatrix.sync.aligned.m8n8.x4.shared.b16 "
                                 "{%0,%1,%2,%3}, [%4];"
                                 : "=r"(w1F[mi][0]), "=r"(w1F[mi][1]),
                                   "=r"(w1F[mi][2]), "=r"(w1F[mi][3])
                                 : "r"(base + OFF_W1 + ra));
                    asm volatile("ldmatrix.sync.aligned.m8n8.x4.shared.b16 "
                                 "{%0,%1,%2,%3}, [%4];"
                                 : "=r"(w2F[mi][0]), "=r"(w2F[mi][1]),
                                   "=r"(w2F[mi][2]), "=r"(w2F[mi][3])
                                 : "r"(base + OFF_W2 + ra));
                }
#pragma unroll
                for (int g = 0; g < 2; g++) {
                    uint32_t rb = (uint32_t)((wn * 32 + g * 16 + bRow) * STRIDE +
                                             ks + bCol);
                    asm volatile("ldmatrix.sync.aligned.m8n8.x4.shared.b16 "
                                 "{%0,%1,%2,%3}, [%4];"
                                 : "=r"(b1F[g * 2][0]), "=r"(b1F[g * 2][1]),
                                   "=r"(b1F[g * 2 + 1][0]), "=r"(b1F[g * 2 + 1][1])
                                 : "r"(base + OFF_A1 + rb));
                    asm volatile("ldmatrix.sync.aligned.m8n8.x4.shared.b16 "
                                 "{%0,%1,%2,%3}, [%4];"
                                 : "=r"(b2F[g * 2][0]), "=r"(b2F[g * 2][1]),
                                   "=r"(b2F[g * 2 + 1][0]), "=r"(b2F[g * 2 + 1][1])
                                 : "r"(base + OFF_A2 + rb));
                }
#pragma unroll
                for (int mi = 0; mi < 2; mi++)
#pragma unroll
                    for (int nj = 0; nj < 4; nj++) {
#define IMMA(ACC, AF, BF)                                                     \
    asm volatile(                                                             \
        "mma.sync.aligned.m16n8k32.row.col.s32.s8.s8.s32 "                    \
        "{%0,%1,%2,%3}, {%4,%5,%6,%7}, {%8,%9}, {%0,%1,%2,%3};"               \
        : "+r"(ACC[mi][nj][0]), "+r"(ACC[mi][nj][1]),                          \
          "+r"(ACC[mi][nj][2]), "+r"(ACC[mi][nj][3])                           \
        : "r"(AF[mi][0]), "r"(AF[mi][1]), "r"(AF[mi][2]), "r"(AF[mi][3]),      \
          "r"(BF[nj][0]), "r"(BF[nj][1]))
                        IMMA(accM, w1F, b1F);
                        IMMA(accX, w1F, b2F);
                        IMMA(accX, w2F, b1F);
#undef IMMA
                    }
            }
            __syncthreads();
            if (c + 2 < NCHUNK) issue(c + 2, c & 1);
        }

        // Epilogue: dequant + leaky ReLU + float2 stores
        const float SLOPE = 11.0f / 48.0f;
        const float INV128 = 1.0f / 128.0f;
        int qrow = lane >> 2;
        int qcol = (lane & 3) * 2;
#pragma unroll
        for (int mi = 0; mi < 2; mi++) {
            int e0 = m0 + wm * 32 + mi * 16 + qrow;
            float sw0 = g_sw[e0], sw1 = g_sw[e0 + 8];
#pragma unroll
            for (int nj = 0; nj < 4; nj++) {
                int b = n0 + wn * 32 + nj * 8 + qcol;
                float sa0 = g_sa[b], sa1 = g_sa[b + 1];
                float y0 = ((float)accM[mi][nj][0] + (float)accX[mi][nj][0] * INV128) * sw0 * sa0;
                float y1 = ((float)accM[mi][nj][1] + (float)accX[mi][nj][1] * INV128) * sw0 * sa1;
                float y2 = ((float)accM[mi][nj][2] + (float)accX[mi][nj][2] * INV128) * sw1 * sa0;
                float y3 = ((float)accM[mi][nj][3] + (float)accX[mi][nj][3] * INV128) * sw1 * sa1;
                float2 v0, v1;
                v0.x = (y0 >= 0.f) ? y0 : y0 * SLOPE;
                v0.y = (y1 >= 0.f) ? y1 : y1 * SLOPE;
                v1.x = (y2 >= 0.f) ? y2 : y2 * SLOPE;
                v1.y = (y3 >= 0.f) ? y3 : y3 * SLOPE;
                *(float2*)(out + (size_t)e0 * NB + b) = v0;
                *(float2*)(out + (size_t)(e0 + 8) * NB + b) = v1;
            }
        }
    }
}

// --------------------------------------------------------------------------
// Launch: zero flags -> persistent fused kernel. Graph-capturable,
// allocation-free, deterministic.
// --------------------------------------------------------------------------
extern "C" void kernel_launch(void* const* d_in, const int* in_sizes, int n_in,
                              void* d_out, int out_size) {
    const float* feat = (const float*)d_in[0];
    const float* W    = (const float*)d_in[1];
    const int*   idxw = (const int*)d_in[2];
    float* out = (float*)d_out;

    int smCount = 0;
    cudaDeviceGetAttribute(&smCount, cudaDevAttrMultiProcessorCount, 0);
    int G = smCount * 2;

    cudaFuncSetAttribute(k_fused, cudaFuncAttributeMaxDynamicSharedMemorySize,
                         SMEMSZ);

    k_zero<<<1, 512>>>();
    k_fused<<<G, 256, SMEMSZ>>>(feat, W, idxw, out);
}